// round 15
// baseline (speedup 1.0000x reference)
#include <cuda_runtime.h>
#include <cuda_bf16.h>
#include <cuda_fp16.h>
#include <math.h>
#include <cstdint>

#define T_SEQ 2048
#define C_DIM 1024
#define C3    3072
#define NH    16
#define HD    64
#define M_ROWS 4096   // B*T

// ---------------------------------------------------------------------------
// Scratch (static device arrays — allocation-guard safe)
// ---------------------------------------------------------------------------
__device__ float g_qkv[(size_t)M_ROWS * C3];
__device__ __nv_bfloat16 g_xh[(size_t)M_ROWS * C_DIM], g_xl[(size_t)M_ROWS * C_DIM];
__device__ __nv_bfloat16 g_wqh[(size_t)C3 * C_DIM],    g_wql[(size_t)C3 * C_DIM];
// fp16 planes for flash + proj
__device__ __half g_qh[(size_t)2 * NH * T_SEQ * HD], g_ql[(size_t)2 * NH * T_SEQ * HD];
__device__ __half g_k16[(size_t)2 * NH * T_SEQ * HD];
__device__ __half g_v16[(size_t)2 * NH * T_SEQ * HD];
__device__ __half g_yh[(size_t)M_ROWS * C_DIM], g_yl[(size_t)M_ROWS * C_DIM];
__device__ __half g_wp16[(size_t)C_DIM * C_DIM];

// ---------------------------------------------------------------------------
// helpers
// ---------------------------------------------------------------------------
__device__ __forceinline__ uint32_t smem_u32(const void* p) {
    uint32_t a;
    asm("{ .reg .u64 t; cvta.to.shared.u64 t, %1; cvt.u32.u64 %0, t; }"
        : "=r"(a) : "l"(p));
    return a;
}
__device__ __forceinline__ void mma_bf16(float* c, const uint32_t* a, const uint32_t* b) {
    asm volatile(
        "mma.sync.aligned.m16n8k16.row.col.f32.bf16.bf16.f32 "
        "{%0,%1,%2,%3}, {%4,%5,%6,%7}, {%8,%9}, {%0,%1,%2,%3};"
        : "+f"(c[0]), "+f"(c[1]), "+f"(c[2]), "+f"(c[3])
        : "r"(a[0]), "r"(a[1]), "r"(a[2]), "r"(a[3]), "r"(b[0]), "r"(b[1]));
}
__device__ __forceinline__ void mma2_bf16(float* c, const uint32_t* a, uint32_t b0, uint32_t b1) {
    asm volatile(
        "mma.sync.aligned.m16n8k16.row.col.f32.bf16.bf16.f32 "
        "{%0,%1,%2,%3}, {%4,%5,%6,%7}, {%8,%9}, {%0,%1,%2,%3};"
        : "+f"(c[0]), "+f"(c[1]), "+f"(c[2]), "+f"(c[3])
        : "r"(a[0]), "r"(a[1]), "r"(a[2]), "r"(a[3]), "r"(b0), "r"(b1));
}
__device__ __forceinline__ void mma_f16(float* c, const uint32_t* a, const uint32_t* b) {
    asm volatile(
        "mma.sync.aligned.m16n8k16.row.col.f32.f16.f16.f32 "
        "{%0,%1,%2,%3}, {%4,%5,%6,%7}, {%8,%9}, {%0,%1,%2,%3};"
        : "+f"(c[0]), "+f"(c[1]), "+f"(c[2]), "+f"(c[3])
        : "r"(a[0]), "r"(a[1]), "r"(a[2]), "r"(a[3]), "r"(b[0]), "r"(b[1]));
}
__device__ __forceinline__ void mma2_f16(float* c, const uint32_t* a, uint32_t b0, uint32_t b1) {
    asm volatile(
        "mma.sync.aligned.m16n8k16.row.col.f32.f16.f16.f32 "
        "{%0,%1,%2,%3}, {%4,%5,%6,%7}, {%8,%9}, {%0,%1,%2,%3};"
        : "+f"(c[0]), "+f"(c[1]), "+f"(c[2]), "+f"(c[3])
        : "r"(a[0]), "r"(a[1]), "r"(a[2]), "r"(a[3]), "r"(b0), "r"(b1));
}
__device__ __forceinline__ void ldmx4(uint32_t* r, uint32_t addr) {
    asm volatile("ldmatrix.sync.aligned.m8n8.x4.shared.b16 {%0,%1,%2,%3}, [%4];"
        : "=r"(r[0]), "=r"(r[1]), "=r"(r[2]), "=r"(r[3]) : "r"(addr));
}
__device__ __forceinline__ void ldmx4t(uint32_t* r, uint32_t addr) {
    asm volatile("ldmatrix.sync.aligned.m8n8.x4.trans.shared.b16 {%0,%1,%2,%3}, [%4];"
        : "=r"(r[0]), "=r"(r[1]), "=r"(r[2]), "=r"(r[3]) : "r"(addr));
}
__device__ __forceinline__ float fast_exp2(float x) {
    float r;
    asm("ex2.approx.ftz.f32 %0, %1;" : "=f"(r) : "f"(x));
    return r;
}
// bf16 pack
__device__ __forceinline__ uint32_t pack_hi(float a, float b) {
    __nv_bfloat162 h = __floats2bfloat162_rn(a, b);
    return *(uint32_t*)&h;
}
__device__ __forceinline__ uint32_t pack_lo(float a, float b, uint32_t hi) {
    __nv_bfloat162 h = *(__nv_bfloat162*)&hi;
    float2 f = __bfloat1622float2(h);
    __nv_bfloat162 l = __floats2bfloat162_rn(a - f.x, b - f.y);
    return *(uint32_t*)&l;
}
// fp16 pack
__device__ __forceinline__ uint32_t packh(float a, float b) {
    __half2 h = __floats2half2_rn(a, b);
    return *(uint32_t*)&h;
}
__device__ __forceinline__ uint32_t packh_lo(float a, float b, uint32_t hi) {
    __half2 h = *(__half2*)&hi;
    float2 f = __half22float2(h);
    __half2 l = __floats2half2_rn(a - f.x, b - f.y);
    return *(uint32_t*)&l;
}
__device__ __forceinline__ void cp16(uint32_t dst, const void* src) {
    asm volatile("cp.async.cg.shared.global [%0], [%1], 16;" :: "r"(dst), "l"(src));
}
__device__ __forceinline__ void cp_commit() {
    asm volatile("cp.async.commit_group;" ::: "memory");
}
template <int N>
__device__ __forceinline__ void cp_wait() {
    asm volatile("cp.async.wait_group %0;" :: "n"(N) : "memory");
}

// ---------------------------------------------------------------------------
// pre-passes
// ---------------------------------------------------------------------------
__global__ __launch_bounds__(256) void split_bf16(const float* __restrict__ in,
                                                  __nv_bfloat16* __restrict__ hi,
                                                  __nv_bfloat16* __restrict__ lo,
                                                  int n4) {
    int i = blockIdx.x * blockDim.x + threadIdx.x;
    if (i >= n4) return;
    float4 v = ((const float4*)in)[i];
    uint32_t h0 = pack_hi(v.x, v.y);
    uint32_t h1 = pack_hi(v.z, v.w);
    ((uint2*)hi)[i] = make_uint2(h0, h1);
    ((uint2*)lo)[i] = make_uint2(pack_lo(v.x, v.y, h0), pack_lo(v.z, v.w, h1));
}

__global__ __launch_bounds__(256) void round_f16(const float* __restrict__ in,
                                                 __half* __restrict__ out, int n4) {
    int i = blockIdx.x * blockDim.x + threadIdx.x;
    if (i >= n4) return;
    float4 v = ((const float4*)in)[i];
    ((uint2*)out)[i] = make_uint2(packh(v.x, v.y), packh(v.z, v.w));
}

// ---------------------------------------------------------------------------
// RoPE + split: qkv fp32 -> per-head fp16 planes.
// q: hi/lo (scaled by 1/8*log2e); k, v: single fp16.
// ---------------------------------------------------------------------------
__global__ __launch_bounds__(256) void rope_split(
    const float* __restrict__ qkv,
    __half* __restrict__ qh, __half* __restrict__ ql,
    __half* __restrict__ k16, __half* __restrict__ v16) {
    int idx = blockIdx.x * 256 + threadIdx.x;
    int g = idx & 15;
    int rowh = idx >> 4;
    int t = rowh & (T_SEQ - 1);
    int bh = rowh >> 11;
    int b = bh >> 4, h = bh & 15;
    const float* base = qkv + ((size_t)(b * T_SEQ + t)) * C3 + h * HD + g * 4;
    float4 q = *(const float4*)base;
    float4 k = *(const float4*)(base + C_DIM);
    float4 v = *(const float4*)(base + 2 * C_DIM);
    int d0 = g * 4;
    float th0 = (float)exp((double)d0 * -0.14391156831212787);
    float th1 = (float)exp((double)(d0 + 2) * -0.14391156831212787);
    float s0, c0, s1, c1;
    sincosf((float)t * th0, &s0, &c0);
    sincosf((float)t * th1, &s1, &c1);
    const float qs = 0.125f * 1.4426950408889634f;
    float qx = (q.x * c0 - q.y * s0) * qs, qy = (q.y * c0 + q.x * s0) * qs;
    float qz = (q.z * c1 - q.w * s1) * qs, qw = (q.w * c1 + q.z * s1) * qs;
    float kx = k.x * c0 - k.y * s0, ky = k.y * c0 + k.x * s0;
    float kz = k.z * c1 - k.w * s1, kw = k.w * c1 + k.z * s1;
    size_t oi = (size_t)rowh * 16 + g;
    uint32_t h0 = packh(qx, qy), h1 = packh(qz, qw);
    ((uint2*)qh)[oi] = make_uint2(h0, h1);
    ((uint2*)ql)[oi] = make_uint2(packh_lo(qx, qy, h0), packh_lo(qz, qw, h1));
    ((uint2*)k16)[oi] = make_uint2(packh(kx, ky), packh(kz, kw));
    ((uint2*)v16)[oi] = make_uint2(packh(v.x, v.y), packh(v.z, v.w));
}

// ---------------------------------------------------------------------------
// QKV GEMM (NT): bf16 3-term, CTA 128x128, 4 warps (2x2 of 64x64), K-tile 32,
// 3-stage cp.async ring w/ uniform group accounting. (Known-good from R14.)
// ---------------------------------------------------------------------------
#define GSTG3 36864   // 256 rows * 144B per stage

__global__ __launch_bounds__(128, 2) void gemm_bf16_v3(
    const __nv_bfloat16* __restrict__ Ah, const __nv_bfloat16* __restrict__ Al,
    const __nv_bfloat16* __restrict__ Bh, const __nv_bfloat16* __restrict__ Bl,
    float* __restrict__ C, int M, int N, int K) {
    extern __shared__ char smem[];
    const uint32_t sb = smem_u32(smem);
    const int tid = threadIdx.x;
    const int wid = tid >> 5, lane = tid & 31;
    const int wm = wid >> 1, wn = wid & 1;
    const int m0 = blockIdx.y * 128, n0 = blockIdx.x * 128;

    float acc[4][8][4];
#pragma unroll
    for (int i = 0; i < 4; i++)
#pragma unroll
        for (int j = 0; j < 8; j++)
#pragma unroll
            for (int r = 0; r < 4; r++) acc[i][j][r] = 0.f;

    auto issue_tile = [&](int kt, int stg) {
        uint32_t base = sb + stg * GSTG3;
#pragma unroll
        for (int i = 0; i < 16; i++) {
            int c = i * 128 + tid;
            int row = c >> 3, ch = c & 7;
            uint32_t dst = base + row * 144 + ch * 16;
            const __nv_bfloat16* src;
            if (row < 128)
                src = (ch < 4 ? Ah : Al) + (size_t)(m0 + row) * K + kt + (ch & 3) * 8;
            else
                src = (ch < 4 ? Bh : Bl) + (size_t)(n0 + row - 128) * K + kt + (ch & 3) * 8;
            cp16(dst, src);
        }
        cp_commit();
    };

    const int nk = K >> 5;
    issue_tile(0, 0);
    issue_tile(32, 1);

    const uint32_t a_off = (uint32_t)((wm * 64 + (lane & 15)) * 144 + (lane >> 4) * 16);
    const uint32_t b_off = (uint32_t)((128 + wn * 64 + (lane & 15)) * 144 + (lane >> 4) * 16);

    int stg = 0;
    for (int kt = 0; kt < nk; kt++) {
        cp_wait<1>();
        __syncthreads();
        if (kt + 2 < nk) {
            int ns = stg + 2; if (ns >= 3) ns -= 3;
            issue_tile((kt + 2) << 5, ns);
        } else {
            cp_commit();
        }

        const uint32_t tb = sb + stg * GSTG3;
#pragma unroll
        for (int ks = 0; ks < 2; ks++) {
            uint32_t bh4[4][4], bl4[4][4];
#pragma unroll
            for (int np = 0; np < 4; np++) {
                uint32_t ba = tb + b_off + np * (16 * 144) + ks * 32;
                ldmx4(bh4[np], ba);
                ldmx4(bl4[np], ba + 64);
            }
#pragma unroll
            for (int mt = 0; mt < 4; mt++) {
                uint32_t ahi[4], alo[4];
                uint32_t aa = tb + a_off + mt * (16 * 144) + ks * 32;
                ldmx4(ahi, aa);
                ldmx4(alo, aa + 64);
#pragma unroll
                for (int nt = 0; nt < 8; nt++)
                    mma2_bf16(acc[mt][nt], ahi, bh4[nt >> 1][nt & 1], bh4[nt >> 1][(nt & 1) + 2]);
#pragma unroll
                for (int nt = 0; nt < 8; nt++)
                    mma2_bf16(acc[mt][nt], alo, bh4[nt >> 1][nt & 1], bh4[nt >> 1][(nt & 1) + 2]);
#pragma unroll
                for (int nt = 0; nt < 8; nt++)
                    mma2_bf16(acc[mt][nt], ahi, bl4[nt >> 1][nt & 1], bl4[nt >> 1][(nt & 1) + 2]);
            }
        }
        if (++stg == 3) stg = 0;
    }
    cp_wait<0>();

#pragma unroll
    for (int mt = 0; mt < 4; mt++) {
#pragma unroll
        for (int nt = 0; nt < 8; nt++) {
            int gm = m0 + wm * 64 + mt * 16 + (lane >> 2);
            int gn = n0 + wn * 64 + nt * 8 + (lane & 3) * 2;
            *(float2*)&C[(size_t)gm * N + gn] = make_float2(acc[mt][nt][0], acc[mt][nt][1]);
            *(float2*)&C[(size_t)(gm + 8) * N + gn] = make_float2(acc[mt][nt][2], acc[mt][nt][3]);
        }
    }
}

// ---------------------------------------------------------------------------
// Proj GEMM (NT): fp16 2-term asymmetric. A = yh+yl (fp16), B = w fp16 single.
// Same skeleton as gemm_bf16_v3; B rows carry only 64B of data.
// ---------------------------------------------------------------------------
__global__ __launch_bounds__(128, 2) void gemm_f16_2t(
    const __half* __restrict__ Ah, const __half* __restrict__ Al,
    const __half* __restrict__ Bh,
    float* __restrict__ C, int M, int N, int K) {
    extern __shared__ char smem[];
    const uint32_t sb = smem_u32(smem);
    const int tid = threadIdx.x;
    const int wid = tid >> 5, lane = tid & 31;
    const int wm = wid >> 1, wn = wid & 1;
    const int m0 = blockIdx.y * 128, n0 = blockIdx.x * 128;

    float acc[4][8][4];
#pragma unroll
    for (int i = 0; i < 4; i++)
#pragma unroll
        for (int j = 0; j < 8; j++)
#pragma unroll
            for (int r = 0; r < 4; r++) acc[i][j][r] = 0.f;

    auto issue_tile = [&](int kt, int stg) {
        uint32_t base = sb + stg * GSTG3;
#pragma unroll
        for (int i = 0; i < 12; i++) {   // 1024 A-chunks + 512 B-chunks
            int c = i * 128 + tid;
            const __half* src;
            uint32_t dst;
            if (c < 1024) {
                int row = c >> 3, ch = c & 7;
                dst = base + row * 144 + ch * 16;
                src = (ch < 4 ? Ah : Al) + (size_t)(m0 + row) * K + kt + (ch & 3) * 8;
            } else {
                int cc = c - 1024;
                int row = 128 + (cc >> 2), ch = cc & 3;
                dst = base + row * 144 + ch * 16;
                src = Bh + (size_t)(n0 + row - 128) * K + kt + ch * 8;
            }
            cp16(dst, src);
        }
        cp_commit();
    };

    const int nk = K >> 5;
    issue_tile(0, 0);
    issue_tile(32, 1);

    const uint32_t a_off = (uint32_t)((wm * 64 + (lane & 15)) * 144 + (lane >> 4) * 16);
    const uint32_t b_off = (uint32_t)((128 + wn * 64 + (lane & 15)) * 144 + (lane >> 4) * 16);

    int stg = 0;
    for (int kt = 0; kt < nk; kt++) {
        cp_wait<1>();
        __syncthreads();
        if (kt + 2 < nk) {
            int ns = stg + 2; if (ns >= 3) ns -= 3;
            issue_tile((kt + 2) << 5, ns);
        } else {
            cp_commit();
        }

        const uint32_t tb = sb + stg * GSTG3;
#pragma unroll
        for (int ks = 0; ks < 2; ks++) {
            uint32_t bh4[4][4];
#pragma unroll
            for (int np = 0; np < 4; np++)
                ldmx4(bh4[np], tb + b_off + np * (16 * 144) + ks * 32);
#pragma unroll
            for (int mt = 0; mt < 4; mt++) {
                uint32_t ahi[4], alo[4];
                uint32_t aa = tb + a_off + mt * (16 * 144) + ks * 32;
                ldmx4(ahi, aa);
                ldmx4(alo, aa + 64);
#pragma unroll
                for (int nt = 0; nt < 8; nt++)
                    mma2_f16(acc[mt][nt], ahi, bh4[nt >> 1][nt & 1], bh4[nt >> 1][(nt & 1) + 2]);
#pragma unroll
                for (int nt = 0; nt < 8; nt++)
                    mma2_f16(acc[mt][nt], alo, bh4[nt >> 1][nt & 1], bh4[nt >> 1][(nt & 1) + 2]);
            }
        }
        if (++stg == 3) stg = 0;
    }
    cp_wait<0>();

#pragma unroll
    for (int mt = 0; mt < 4; mt++) {
#pragma unroll
        for (int nt = 0; nt < 8; nt++) {
            int gm = m0 + wm * 64 + mt * 16 + (lane >> 2);
            int gn = n0 + wn * 64 + nt * 8 + (lane & 3) * 2;
            *(float2*)&C[(size_t)gm * N + gn] = make_float2(acc[mt][nt][0], acc[mt][nt][1]);
            *(float2*)&C[(size_t)(gm + 8) * N + gn] = make_float2(acc[mt][nt][2], acc[mt][nt][3]);
        }
    }
}

// ---------------------------------------------------------------------------
// Flash attention, fp16 2-term. Q 128x64/CTA (8 warps x 16 rows), K/V 64x64.
// Q split hi/lo; K, V single fp16. K rows 0-63, V rows 64-127, 144B rows.
// 2-stage cp.async, single sync/tile, pair-interleaved MMA chains.
// ---------------------------------------------------------------------------
#define FSTAGE 18432   // 128 rows * 144B
#define VOFF   (64 * 144)

__global__ __launch_bounds__(256, 2) void flash_f16(
    const __half* __restrict__ qh, const __half* __restrict__ ql,
    const __half* __restrict__ k16, const __half* __restrict__ v16,
    __half* __restrict__ yh, __half* __restrict__ yl) {
    extern __shared__ char smem[];
    const uint32_t sb = smem_u32(smem);
    const int tid = threadIdx.x;
    const int wid = tid >> 5, lane = tid & 31;
    const int qi = gridDim.x - 1 - blockIdx.x;
    const int q0 = qi * 128;
    const int bh = blockIdx.y;
    const size_t hT = (size_t)bh << 11;

    // ---- stage Q into stage area (rows 272B: hi 128B | lo 128B | pad) ----
#pragma unroll
    for (int i = 0; i < 8; i++) {
        int c = i * 256 + tid;
        int row = c >> 4, ch = c & 15;
        uint32_t dst = sb + row * 272 + ch * 16;
        const __half* src = (ch < 8 ? qh : ql) + (hT + q0 + row) * HD + (ch & 7) * 8;
        cp16(dst, src);
    }
    cp_commit();
    cp_wait<0>();
    __syncthreads();

    uint32_t qfh[4][4], qfl[4][4];
    {
        uint32_t qaddr = sb + (wid * 16 + (lane & 15)) * 272 + (lane >> 4) * 16;
#pragma unroll
        for (int kc = 0; kc < 4; kc++) {
            ldmx4(qfh[kc], qaddr + kc * 32);
            ldmx4(qfl[kc], qaddr + kc * 32 + 128);
        }
    }
    __syncthreads();   // Q stage area now reusable as K/V buffers

    auto issue_kv = [&](int k0, int stg) {
        uint32_t base = sb + stg * FSTAGE;
#pragma unroll
        for (int i = 0; i < 4; i++) {
            int c = i * 256 + tid;          // 0..1023
            int row = c >> 3, ch = c & 7;
            uint32_t dst = base + row * 144 + ch * 16;
            const __half* p;
            if (row < 64) p = k16 + (hT + k0 + row) * HD + ch * 8;
            else          p = v16 + (hT + k0 + row - 64) * HD + ch * 8;
            cp16(dst, p);
        }
        cp_commit();
    };
    issue_kv(0, 0);

    float o[8][4];
#pragma unroll
    for (int j = 0; j < 8; j++)
#pragma unroll
        for (int r = 0; r < 4; r++) o[j][r] = 0.f;
    float m0v = -1e30f, m1v = -1e30f, l0v = 0.f, l1v = 0.f;

    const int q0w = q0 + wid * 16;
    const int nkt = 2 * qi + 2;

    for (int kt = 0; kt < nkt; kt++) {
        cp_wait<0>();
        __syncthreads();
        if (kt + 1 < nkt) issue_kv((kt + 1) * 64, (kt + 1) & 1);
        const int k0 = kt * 64;

        if (k0 <= q0w + 15) {
            const uint32_t bb = sb + (kt & 1) * FSTAGE;
            const uint32_t kaddr0 = bb + (lane & 7) * 144 + ((lane >> 3) & 1) * 16 + (lane >> 4) * 32;
            const uint32_t vaddr0 = bb + VOFF + ((lane & 7) + ((lane >> 3) & 3) * 8) * 144;

            // ---- S = Q K^T (pair-interleaved chains; Q split, K single) ----
            float s[8][4];
#pragma unroll
            for (int j = 0; j < 8; j++)
#pragma unroll
                for (int r = 0; r < 4; r++) s[j][r] = 0.f;
#pragma unroll
            for (int kp = 0; kp < 2; kp++) {
#pragma unroll
                for (int jp = 0; jp < 4; jp++) {
                    const int j0 = 2 * jp, j1 = 2 * jp + 1;
                    uint32_t kf0[4], kf1[4];
                    ldmx4(kf0, kaddr0 + j0 * (8 * 144) + kp * 64);
                    ldmx4(kf1, kaddr0 + j1 * (8 * 144) + kp * 64);
                    mma_f16(s[j0], qfh[2 * kp], kf0);       mma_f16(s[j1], qfh[2 * kp], kf1);
                    mma_f16(s[j0], qfl[2 * kp], kf0);       mma_f16(s[j1], qfl[2 * kp], kf1);
                    mma_f16(s[j0], qfh[2 * kp + 1], kf0 + 2); mma_f16(s[j1], qfh[2 * kp + 1], kf1 + 2);
                    mma_f16(s[j0], qfl[2 * kp + 1], kf0 + 2); mma_f16(s[j1], qfl[2 * kp + 1], kf1 + 2);
                }
            }

            // ---- causal mask (diagonal tiles) ----
            if (k0 + 63 > q0w) {
                int gq0 = q0w + (lane >> 2);
                int cb = k0 + 2 * (lane & 3);
#pragma unroll
                for (int j = 0; j < 8; j++) {
                    int c = cb + 8 * j;
                    if (c > gq0)         s[j][0] = -1e30f;
                    if (c + 1 > gq0)     s[j][1] = -1e30f;
                    if (c > gq0 + 8)     s[j][2] = -1e30f;
                    if (c + 1 > gq0 + 8) s[j][3] = -1e30f;
                }
            }

            // ---- online softmax ----
            float mx0 = -1e30f, mx1 = -1e30f;
#pragma unroll
            for (int j = 0; j < 8; j++) {
                mx0 = fmaxf(mx0, fmaxf(s[j][0], s[j][1]));
                mx1 = fmaxf(mx1, fmaxf(s[j][2], s[j][3]));
            }
            mx0 = fmaxf(mx0, __shfl_xor_sync(0xffffffffu, mx0, 1));
            mx0 = fmaxf(mx0, __shfl_xor_sync(0xffffffffu, mx0, 2));
            mx1 = fmaxf(mx1, __shfl_xor_sync(0xffffffffu, mx1, 1));
            mx1 = fmaxf(mx1, __shfl_xor_sync(0xffffffffu, mx1, 2));
            float mn0 = fmaxf(m0v, mx0), mn1 = fmaxf(m1v, mx1);
            float c0 = fast_exp2(m0v - mn0), c1 = fast_exp2(m1v - mn1);
            m0v = mn0; m1v = mn1;

            uint32_t ph[4][4], pl[4][4];
            float rs0 = 0.f, rs1 = 0.f;
#pragma unroll
            for (int j = 0; j < 8; j++) {
                float p0 = fast_exp2(s[j][0] - mn0);
                float p1 = fast_exp2(s[j][1] - mn0);
                float p2 = fast_exp2(s[j][2] - mn1);
                float p3 = fast_exp2(s[j][3] - mn1);
                rs0 += p0 + p1; rs1 += p2 + p3;
                int kc = j >> 1, a0 = (j & 1) * 2;
                uint32_t h01 = packh(p0, p1);
                uint32_t h23 = packh(p2, p3);
                ph[kc][a0] = h01; ph[kc][a0 + 1] = h23;
                pl[kc][a0] = packh_lo(p0, p1, h01);
                pl[kc][a0 + 1] = packh_lo(p2, p3, h23);
            }
            rs0 += __shfl_xor_sync(0xffffffffu, rs0, 1);
            rs0 += __shfl_xor_sync(0xffffffffu, rs0, 2);
            rs1 += __shfl_xor_sync(0xffffffffu, rs1, 1);
            rs1 += __shfl_xor_sync(0xffffffffu, rs1, 2);
            l0v = l0v * c0 + rs0;
            l1v = l1v * c1 + rs1;
#pragma unroll
            for (int j = 0; j < 8; j++) {
                o[j][0] *= c0; o[j][1] *= c0;
                o[j][2] *= c1; o[j][3] *= c1;
            }

            // ---- O += P @ V (P split, V single) ----
#pragma unroll
            for (int kp = 0; kp < 2; kp++) {
#pragma unroll
                for (int jp = 0; jp < 4; jp++) {
                    const int j0 = 2 * jp, j1 = 2 * jp + 1;
                    uint32_t vf0[4], vf1[4];
                    ldmx4t(vf0, vaddr0 + kp * (32 * 144) + j0 * 16);
                    ldmx4t(vf1, vaddr0 + kp * (32 * 144) + j1 * 16);
                    mma_f16(o[j0], ph[2 * kp], vf0);        mma_f16(o[j1], ph[2 * kp], vf1);
                    mma_f16(o[j0], pl[2 * kp], vf0);        mma_f16(o[j1], pl[2 * kp], vf1);
                    mma_f16(o[j0], ph[2 * kp + 1], vf0 + 2); mma_f16(o[j1], ph[2 * kp + 1], vf1 + 2);
                    mma_f16(o[j0], pl[2 * kp + 1], vf0 + 2); mma_f16(o[j1], pl[2 * kp + 1], vf1 + 2);
                }
            }
        }
    }
    cp_wait<0>();

    // ---- epilogue: write y as fp16 hi/lo for the proj GEMM ----
    float inv0 = 1.0f / l0v, inv1 = 1.0f / l1v;
    int gq = q0w + (lane >> 2);
    size_t base0 = ((size_t)((bh >> 4) * T_SEQ + gq)) * C_DIM + (bh & 15) * HD + 2 * (lane & 3);
    size_t base1 = base0 + 8 * C_DIM;
#pragma unroll
    for (int j = 0; j < 8; j++) {
        float f0 = o[j][0] * inv0, f1 = o[j][1] * inv0;
        uint32_t h = packh(f0, f1);
        *(uint32_t*)&yh[base0 + 8 * j] = h;
        *(uint32_t*)&yl[base0 + 8 * j] = packh_lo(f0, f1, h);
        float f2 = o[j][2] * inv1, f3 = o[j][3] * inv1;
        h = packh(f2, f3);
        *(uint32_t*)&yh[base1 + 8 * j] = h;
        *(uint32_t*)&yl[base1 + 8 * j] = packh_lo(f2, f3, h);
    }
}

// ---------------------------------------------------------------------------
extern "C" void kernel_launch(void* const* d_in, const int* in_sizes, int n_in,
                              void* d_out, int out_size) {
    const float* x      = (const float*)d_in[0];
    const float* w_qkv  = (const float*)d_in[1];
    const float* w_proj = (const float*)d_in[2];
    float* out = (float*)d_out;

    float* qkv;
    __nv_bfloat16 *xh, *xl, *wqh, *wql;
    __half *qh, *ql, *k16, *v16, *yh, *yl, *wp16;
    cudaGetSymbolAddress((void**)&qkv, g_qkv);
    cudaGetSymbolAddress((void**)&xh, g_xh);   cudaGetSymbolAddress((void**)&xl, g_xl);
    cudaGetSymbolAddress((void**)&wqh, g_wqh); cudaGetSymbolAddress((void**)&wql, g_wql);
    cudaGetSymbolAddress((void**)&qh, g_qh);   cudaGetSymbolAddress((void**)&ql, g_ql);
    cudaGetSymbolAddress((void**)&k16, g_k16); cudaGetSymbolAddress((void**)&v16, g_v16);
    cudaGetSymbolAddress((void**)&yh, g_yh);   cudaGetSymbolAddress((void**)&yl, g_yl);
    cudaGetSymbolAddress((void**)&wp16, g_wp16);

    cudaFuncSetAttribute(gemm_bf16_v3, cudaFuncAttributeMaxDynamicSharedMemorySize, 3 * GSTG3);
    cudaFuncSetAttribute(gemm_f16_2t, cudaFuncAttributeMaxDynamicSharedMemorySize, 3 * GSTG3);
    cudaFuncSetAttribute(flash_f16, cudaFuncAttributeMaxDynamicSharedMemorySize, 2 * FSTAGE);

    // 0) pre-passes
    split_bf16<<<M_ROWS * C_DIM / 4 / 256, 256>>>(x, xh, xl, M_ROWS * C_DIM / 4);
    split_bf16<<<C3 * C_DIM / 4 / 256, 256>>>(w_qkv, wqh, wql, C3 * C_DIM / 4);
    round_f16<<<C_DIM * C_DIM / 4 / 256, 256>>>(w_proj, wp16, C_DIM * C_DIM / 4);

    // 1) QKV projection (bf16 3-term)
    gemm_bf16_v3<<<dim3(C3 / 128, M_ROWS / 128), 128, 3 * GSTG3>>>(
        xh, xl, wqh, wql, qkv, M_ROWS, C3, C_DIM);

    // 2) RoPE + fp16 split
    rope_split<<<M_ROWS * NH * 16 / 256, 256>>>(qkv, qh, ql, k16, v16);

    // 3) Flash attention (fp16 2-term) -> y fp16 hi/lo
    flash_f16<<<dim3(T_SEQ / 128, 2 * NH), 256, 2 * FSTAGE>>>(
        qh, ql, k16, v16, yh, yl);

    // 4) Output projection (fp16 2-term)
    gemm_f16_2t<<<dim3(C_DIM / 128, M_ROWS / 128), 128, 3 * GSTG3>>>(
        yh, yl, wp16, out, M_ROWS, C_DIM, C_DIM);
}

// round 16
// speedup vs baseline: 1.5405x; 1.5405x over previous
#include <cuda_runtime.h>
#include <cuda_bf16.h>
#include <cuda_fp16.h>
#include <math.h>
#include <cstdint>

#define T_SEQ 2048
#define C_DIM 1024
#define C3    3072
#define NH    16
#define HD    64
#define M_ROWS 4096   // B*T

// ---------------------------------------------------------------------------
// Scratch (static device arrays — allocation-guard safe)
// ---------------------------------------------------------------------------
__device__ float g_qkv[(size_t)M_ROWS * C3];
__device__ __nv_bfloat16 g_xh[(size_t)M_ROWS * C_DIM], g_xl[(size_t)M_ROWS * C_DIM];
__device__ __nv_bfloat16 g_wqh[(size_t)C3 * C_DIM],    g_wql[(size_t)C3 * C_DIM];
// fp16 planes for flash + proj
__device__ __half g_qh[(size_t)2 * NH * T_SEQ * HD], g_ql[(size_t)2 * NH * T_SEQ * HD];
__device__ __half g_k16[(size_t)2 * NH * T_SEQ * HD];
__device__ __half g_v16[(size_t)2 * NH * T_SEQ * HD];
__device__ __half g_yh[(size_t)M_ROWS * C_DIM], g_yl[(size_t)M_ROWS * C_DIM];
__device__ __half g_wp16[(size_t)C_DIM * C_DIM];

// ---------------------------------------------------------------------------
// helpers
// ---------------------------------------------------------------------------
__device__ __forceinline__ uint32_t smem_u32(const void* p) {
    uint32_t a;
    asm("{ .reg .u64 t; cvta.to.shared.u64 t, %1; cvt.u32.u64 %0, t; }"
        : "=r"(a) : "l"(p));
    return a;
}
__device__ __forceinline__ void mma2_bf16(float* c, const uint32_t* a, uint32_t b0, uint32_t b1) {
    asm volatile(
        "mma.sync.aligned.m16n8k16.row.col.f32.bf16.bf16.f32 "
        "{%0,%1,%2,%3}, {%4,%5,%6,%7}, {%8,%9}, {%0,%1,%2,%3};"
        : "+f"(c[0]), "+f"(c[1]), "+f"(c[2]), "+f"(c[3])
        : "r"(a[0]), "r"(a[1]), "r"(a[2]), "r"(a[3]), "r"(b0), "r"(b1));
}
__device__ __forceinline__ void mma_f16(float* c, const uint32_t* a, const uint32_t* b) {
    asm volatile(
        "mma.sync.aligned.m16n8k16.row.col.f32.f16.f16.f32 "
        "{%0,%1,%2,%3}, {%4,%5,%6,%7}, {%8,%9}, {%0,%1,%2,%3};"
        : "+f"(c[0]), "+f"(c[1]), "+f"(c[2]), "+f"(c[3])
        : "r"(a[0]), "r"(a[1]), "r"(a[2]), "r"(a[3]), "r"(b[0]), "r"(b[1]));
}
__device__ __forceinline__ void mma2_f16(float* c, const uint32_t* a, uint32_t b0, uint32_t b1) {
    asm volatile(
        "mma.sync.aligned.m16n8k16.row.col.f32.f16.f16.f32 "
        "{%0,%1,%2,%3}, {%4,%5,%6,%7}, {%8,%9}, {%0,%1,%2,%3};"
        : "+f"(c[0]), "+f"(c[1]), "+f"(c[2]), "+f"(c[3])
        : "r"(a[0]), "r"(a[1]), "r"(a[2]), "r"(a[3]), "r"(b0), "r"(b1));
}
__device__ __forceinline__ void ldmx4(uint32_t* r, uint32_t addr) {
    asm volatile("ldmatrix.sync.aligned.m8n8.x4.shared.b16 {%0,%1,%2,%3}, [%4];"
        : "=r"(r[0]), "=r"(r[1]), "=r"(r[2]), "=r"(r[3]) : "r"(addr));
}
__device__ __forceinline__ void ldmx4t(uint32_t* r, uint32_t addr) {
    asm volatile("ldmatrix.sync.aligned.m8n8.x4.trans.shared.b16 {%0,%1,%2,%3}, [%4];"
        : "=r"(r[0]), "=r"(r[1]), "=r"(r[2]), "=r"(r[3]) : "r"(addr));
}
__device__ __forceinline__ float fast_exp2(float x) {
    float r;
    asm("ex2.approx.ftz.f32 %0, %1;" : "=f"(r) : "f"(x));
    return r;
}
// bf16 pack
__device__ __forceinline__ uint32_t pack_hi(float a, float b) {
    __nv_bfloat162 h = __floats2bfloat162_rn(a, b);
    return *(uint32_t*)&h;
}
__device__ __forceinline__ uint32_t pack_lo(float a, float b, uint32_t hi) {
    __nv_bfloat162 h = *(__nv_bfloat162*)&hi;
    float2 f = __bfloat1622float2(h);
    __nv_bfloat162 l = __floats2bfloat162_rn(a - f.x, b - f.y);
    return *(uint32_t*)&l;
}
// fp16 pack
__device__ __forceinline__ uint32_t packh(float a, float b) {
    __half2 h = __floats2half2_rn(a, b);
    return *(uint32_t*)&h;
}
__device__ __forceinline__ uint32_t packh_lo(float a, float b, uint32_t hi) {
    __half2 h = *(__half2*)&hi;
    float2 f = __half22float2(h);
    __half2 l = __floats2half2_rn(a - f.x, b - f.y);
    return *(uint32_t*)&l;
}
__device__ __forceinline__ void cp16(uint32_t dst, const void* src) {
    asm volatile("cp.async.cg.shared.global [%0], [%1], 16;" :: "r"(dst), "l"(src));
}
__device__ __forceinline__ void cp_commit() {
    asm volatile("cp.async.commit_group;" ::: "memory");
}
template <int N>
__device__ __forceinline__ void cp_wait() {
    asm volatile("cp.async.wait_group %0;" :: "n"(N) : "memory");
}

// ---------------------------------------------------------------------------
// pre-passes
// ---------------------------------------------------------------------------
__global__ __launch_bounds__(256) void split_bf16(const float* __restrict__ in,
                                                  __nv_bfloat16* __restrict__ hi,
                                                  __nv_bfloat16* __restrict__ lo,
                                                  int n4) {
    int i = blockIdx.x * blockDim.x + threadIdx.x;
    if (i >= n4) return;
    float4 v = ((const float4*)in)[i];
    uint32_t h0 = pack_hi(v.x, v.y);
    uint32_t h1 = pack_hi(v.z, v.w);
    ((uint2*)hi)[i] = make_uint2(h0, h1);
    ((uint2*)lo)[i] = make_uint2(pack_lo(v.x, v.y, h0), pack_lo(v.z, v.w, h1));
}

__global__ __launch_bounds__(256) void round_f16(const float* __restrict__ in,
                                                 __half* __restrict__ out, int n4) {
    int i = blockIdx.x * blockDim.x + threadIdx.x;
    if (i >= n4) return;
    float4 v = ((const float4*)in)[i];
    ((uint2*)out)[i] = make_uint2(packh(v.x, v.y), packh(v.z, v.w));
}

// ---------------------------------------------------------------------------
// RoPE + split: qkv fp32 -> per-head fp16 planes.
// q: hi/lo (scaled by 1/8*log2e); k, v: single fp16.
// ---------------------------------------------------------------------------
__global__ __launch_bounds__(256) void rope_split(
    const float* __restrict__ qkv,
    __half* __restrict__ qh, __half* __restrict__ ql,
    __half* __restrict__ k16, __half* __restrict__ v16) {
    int idx = blockIdx.x * 256 + threadIdx.x;
    int g = idx & 15;
    int rowh = idx >> 4;
    int t = rowh & (T_SEQ - 1);
    int bh = rowh >> 11;
    int b = bh >> 4, h = bh & 15;
    const float* base = qkv + ((size_t)(b * T_SEQ + t)) * C3 + h * HD + g * 4;
    float4 q = *(const float4*)base;
    float4 k = *(const float4*)(base + C_DIM);
    float4 v = *(const float4*)(base + 2 * C_DIM);
    int d0 = g * 4;
    float th0 = (float)exp((double)d0 * -0.14391156831212787);
    float th1 = (float)exp((double)(d0 + 2) * -0.14391156831212787);
    float s0, c0, s1, c1;
    sincosf((float)t * th0, &s0, &c0);
    sincosf((float)t * th1, &s1, &c1);
    const float qs = 0.125f * 1.4426950408889634f;
    float qx = (q.x * c0 - q.y * s0) * qs, qy = (q.y * c0 + q.x * s0) * qs;
    float qz = (q.z * c1 - q.w * s1) * qs, qw = (q.w * c1 + q.z * s1) * qs;
    float kx = k.x * c0 - k.y * s0, ky = k.y * c0 + k.x * s0;
    float kz = k.z * c1 - k.w * s1, kw = k.w * c1 + k.z * s1;
    size_t oi = (size_t)rowh * 16 + g;
    uint32_t h0 = packh(qx, qy), h1 = packh(qz, qw);
    ((uint2*)qh)[oi] = make_uint2(h0, h1);
    ((uint2*)ql)[oi] = make_uint2(packh_lo(qx, qy, h0), packh_lo(qz, qw, h1));
    ((uint2*)k16)[oi] = make_uint2(packh(kx, ky), packh(kz, kw));
    ((uint2*)v16)[oi] = make_uint2(packh(v.x, v.y), packh(v.z, v.w));
}

// ---------------------------------------------------------------------------
// QKV GEMM (NT): bf16 3-term, CTA 128x128, 4 warps (2x2 of 64x64), K-tile 32,
// 3-stage cp.async ring w/ uniform group accounting. (Known-good from R14.)
// ---------------------------------------------------------------------------
#define GSTG3 36864   // 256 rows * 144B per stage

__global__ __launch_bounds__(128, 2) void gemm_bf16_v3(
    const __nv_bfloat16* __restrict__ Ah, const __nv_bfloat16* __restrict__ Al,
    const __nv_bfloat16* __restrict__ Bh, const __nv_bfloat16* __restrict__ Bl,
    float* __restrict__ C, int M, int N, int K) {
    extern __shared__ char smem[];
    const uint32_t sb = smem_u32(smem);
    const int tid = threadIdx.x;
    const int wid = tid >> 5, lane = tid & 31;
    const int wm = wid >> 1, wn = wid & 1;
    const int m0 = blockIdx.y * 128, n0 = blockIdx.x * 128;

    float acc[4][8][4];
#pragma unroll
    for (int i = 0; i < 4; i++)
#pragma unroll
        for (int j = 0; j < 8; j++)
#pragma unroll
            for (int r = 0; r < 4; r++) acc[i][j][r] = 0.f;

    auto issue_tile = [&](int kt, int stg) {
        uint32_t base = sb + stg * GSTG3;
#pragma unroll
        for (int i = 0; i < 16; i++) {
            int c = i * 128 + tid;
            int row = c >> 3, ch = c & 7;
            uint32_t dst = base + row * 144 + ch * 16;
            const __nv_bfloat16* src;
            if (row < 128)
                src = (ch < 4 ? Ah : Al) + (size_t)(m0 + row) * K + kt + (ch & 3) * 8;
            else
                src = (ch < 4 ? Bh : Bl) + (size_t)(n0 + row - 128) * K + kt + (ch & 3) * 8;
            cp16(dst, src);
        }
        cp_commit();
    };

    const int nk = K >> 5;
    issue_tile(0, 0);
    issue_tile(32, 1);

    const uint32_t a_off = (uint32_t)((wm * 64 + (lane & 15)) * 144 + (lane >> 4) * 16);
    const uint32_t b_off = (uint32_t)((128 + wn * 64 + (lane & 15)) * 144 + (lane >> 4) * 16);

    int stg = 0;
    for (int kt = 0; kt < nk; kt++) {
        cp_wait<1>();
        __syncthreads();
        if (kt + 2 < nk) {
            int ns = stg + 2; if (ns >= 3) ns -= 3;
            issue_tile((kt + 2) << 5, ns);
        } else {
            cp_commit();
        }

        const uint32_t tb = sb + stg * GSTG3;
#pragma unroll
        for (int ks = 0; ks < 2; ks++) {
            uint32_t bh4[4][4], bl4[4][4];
#pragma unroll
            for (int np = 0; np < 4; np++) {
                uint32_t ba = tb + b_off + np * (16 * 144) + ks * 32;
                ldmx4(bh4[np], ba);
                ldmx4(bl4[np], ba + 64);
            }
#pragma unroll
            for (int mt = 0; mt < 4; mt++) {
                uint32_t ahi[4], alo[4];
                uint32_t aa = tb + a_off + mt * (16 * 144) + ks * 32;
                ldmx4(ahi, aa);
                ldmx4(alo, aa + 64);
#pragma unroll
                for (int nt = 0; nt < 8; nt++)
                    mma2_bf16(acc[mt][nt], ahi, bh4[nt >> 1][nt & 1], bh4[nt >> 1][(nt & 1) + 2]);
#pragma unroll
                for (int nt = 0; nt < 8; nt++)
                    mma2_bf16(acc[mt][nt], alo, bh4[nt >> 1][nt & 1], bh4[nt >> 1][(nt & 1) + 2]);
#pragma unroll
                for (int nt = 0; nt < 8; nt++)
                    mma2_bf16(acc[mt][nt], ahi, bl4[nt >> 1][nt & 1], bl4[nt >> 1][(nt & 1) + 2]);
            }
        }
        if (++stg == 3) stg = 0;
    }
    cp_wait<0>();

#pragma unroll
    for (int mt = 0; mt < 4; mt++) {
#pragma unroll
        for (int nt = 0; nt < 8; nt++) {
            int gm = m0 + wm * 64 + mt * 16 + (lane >> 2);
            int gn = n0 + wn * 64 + nt * 8 + (lane & 3) * 2;
            *(float2*)&C[(size_t)gm * N + gn] = make_float2(acc[mt][nt][0], acc[mt][nt][1]);
            *(float2*)&C[(size_t)(gm + 8) * N + gn] = make_float2(acc[mt][nt][2], acc[mt][nt][3]);
        }
    }
}

// ---------------------------------------------------------------------------
// Proj GEMM (NT): fp16 2-term asymmetric. A = yh+yl (fp16), B = w fp16 single.
// ---------------------------------------------------------------------------
__global__ __launch_bounds__(128, 2) void gemm_f16_2t(
    const __half* __restrict__ Ah, const __half* __restrict__ Al,
    const __half* __restrict__ Bh,
    float* __restrict__ C, int M, int N, int K) {
    extern __shared__ char smem[];
    const uint32_t sb = smem_u32(smem);
    const int tid = threadIdx.x;
    const int wid = tid >> 5, lane = tid & 31;
    const int wm = wid >> 1, wn = wid & 1;
    const int m0 = blockIdx.y * 128, n0 = blockIdx.x * 128;

    float acc[4][8][4];
#pragma unroll
    for (int i = 0; i < 4; i++)
#pragma unroll
        for (int j = 0; j < 8; j++)
#pragma unroll
            for (int r = 0; r < 4; r++) acc[i][j][r] = 0.f;

    auto issue_tile = [&](int kt, int stg) {
        uint32_t base = sb + stg * GSTG3;
#pragma unroll
        for (int i = 0; i < 12; i++) {   // 1024 A-chunks + 512 B-chunks
            int c = i * 128 + tid;
            const __half* src;
            uint32_t dst;
            if (c < 1024) {
                int row = c >> 3, ch = c & 7;
                dst = base + row * 144 + ch * 16;
                src = (ch < 4 ? Ah : Al) + (size_t)(m0 + row) * K + kt + (ch & 3) * 8;
            } else {
                int cc = c - 1024;
                int row = 128 + (cc >> 2), ch = cc & 3;
                dst = base + row * 144 + ch * 16;
                src = Bh + (size_t)(n0 + row - 128) * K + kt + ch * 8;
            }
            cp16(dst, src);
        }
        cp_commit();
    };

    const int nk = K >> 5;
    issue_tile(0, 0);
    issue_tile(32, 1);

    const uint32_t a_off = (uint32_t)((wm * 64 + (lane & 15)) * 144 + (lane >> 4) * 16);
    const uint32_t b_off = (uint32_t)((128 + wn * 64 + (lane & 15)) * 144 + (lane >> 4) * 16);

    int stg = 0;
    for (int kt = 0; kt < nk; kt++) {
        cp_wait<1>();
        __syncthreads();
        if (kt + 2 < nk) {
            int ns = stg + 2; if (ns >= 3) ns -= 3;
            issue_tile((kt + 2) << 5, ns);
        } else {
            cp_commit();
        }

        const uint32_t tb = sb + stg * GSTG3;
#pragma unroll
        for (int ks = 0; ks < 2; ks++) {
            uint32_t bh4[4][4];
#pragma unroll
            for (int np = 0; np < 4; np++)
                ldmx4(bh4[np], tb + b_off + np * (16 * 144) + ks * 32);
#pragma unroll
            for (int mt = 0; mt < 4; mt++) {
                uint32_t ahi[4], alo[4];
                uint32_t aa = tb + a_off + mt * (16 * 144) + ks * 32;
                ldmx4(ahi, aa);
                ldmx4(alo, aa + 64);
#pragma unroll
                for (int nt = 0; nt < 8; nt++)
                    mma2_f16(acc[mt][nt], ahi, bh4[nt >> 1][nt & 1], bh4[nt >> 1][(nt & 1) + 2]);
#pragma unroll
                for (int nt = 0; nt < 8; nt++)
                    mma2_f16(acc[mt][nt], alo, bh4[nt >> 1][nt & 1], bh4[nt >> 1][(nt & 1) + 2]);
            }
        }
        if (++stg == 3) stg = 0;
    }
    cp_wait<0>();

#pragma unroll
    for (int mt = 0; mt < 4; mt++) {
#pragma unroll
        for (int nt = 0; nt < 8; nt++) {
            int gm = m0 + wm * 64 + mt * 16 + (lane >> 2);
            int gn = n0 + wn * 64 + nt * 8 + (lane & 3) * 2;
            *(float2*)&C[(size_t)gm * N + gn] = make_float2(acc[mt][nt][0], acc[mt][nt][1]);
            *(float2*)&C[(size_t)(gm + 8) * N + gn] = make_float2(acc[mt][nt][2], acc[mt][nt][3]);
        }
    }
}

// ---------------------------------------------------------------------------
// Flash attention, fp16 2-term. Q 128x64/CTA (8 warps x 16 rows), K/V 64x64.
// Q split hi/lo; K, V single fp16. K rows 0-63, V rows 64-127, 144B rows.
// 2-stage cp.async, single sync/tile. NO register cap (spills are deadly).
// ---------------------------------------------------------------------------
#define FSTAGE 18432   // 128 rows * 144B
#define VOFF   (64 * 144)

__global__ __launch_bounds__(256) void flash_f16(
    const __half* __restrict__ qh, const __half* __restrict__ ql,
    const __half* __restrict__ k16, const __half* __restrict__ v16,
    __half* __restrict__ yh, __half* __restrict__ yl) {
    extern __shared__ char smem[];
    const uint32_t sb = smem_u32(smem);
    const int tid = threadIdx.x;
    const int wid = tid >> 5, lane = tid & 31;
    const int qi = gridDim.x - 1 - blockIdx.x;
    const int q0 = qi * 128;
    const int bh = blockIdx.y;
    const size_t hT = (size_t)bh << 11;

    // ---- stage Q into stage area (rows 272B: hi 128B | lo 128B | pad) ----
#pragma unroll
    for (int i = 0; i < 8; i++) {
        int c = i * 256 + tid;
        int row = c >> 4, ch = c & 15;
        uint32_t dst = sb + row * 272 + ch * 16;
        const __half* src = (ch < 8 ? qh : ql) + (hT + q0 + row) * HD + (ch & 7) * 8;
        cp16(dst, src);
    }
    cp_commit();
    cp_wait<0>();
    __syncthreads();

    uint32_t qfh[4][4], qfl[4][4];
    {
        uint32_t qaddr = sb + (wid * 16 + (lane & 15)) * 272 + (lane >> 4) * 16;
#pragma unroll
        for (int kc = 0; kc < 4; kc++) {
            ldmx4(qfh[kc], qaddr + kc * 32);
            ldmx4(qfl[kc], qaddr + kc * 32 + 128);
        }
    }
    __syncthreads();   // Q stage area now reusable as K/V buffers

    auto issue_kv = [&](int k0, int stg) {
        uint32_t base = sb + stg * FSTAGE;
#pragma unroll
        for (int i = 0; i < 4; i++) {
            int c = i * 256 + tid;          // 0..1023
            int row = c >> 3, ch = c & 7;
            uint32_t dst = base + row * 144 + ch * 16;
            const __half* p;
            if (row < 64) p = k16 + (hT + k0 + row) * HD + ch * 8;
            else          p = v16 + (hT + k0 + row - 64) * HD + ch * 8;
            cp16(dst, p);
        }
        cp_commit();
    };
    issue_kv(0, 0);

    float o[8][4];
#pragma unroll
    for (int j = 0; j < 8; j++)
#pragma unroll
        for (int r = 0; r < 4; r++) o[j][r] = 0.f;
    float m0v = -1e30f, m1v = -1e30f, l0v = 0.f, l1v = 0.f;

    const int q0w = q0 + wid * 16;
    const int nkt = 2 * qi + 2;

    for (int kt = 0; kt < nkt; kt++) {
        cp_wait<0>();
        __syncthreads();
        if (kt + 1 < nkt) issue_kv((kt + 1) * 64, (kt + 1) & 1);
        const int k0 = kt * 64;

        if (k0 <= q0w + 15) {
            const uint32_t bb = sb + (kt & 1) * FSTAGE;
            const uint32_t kaddr0 = bb + (lane & 7) * 144 + ((lane >> 3) & 1) * 16 + (lane >> 4) * 32;
            const uint32_t vaddr0 = bb + VOFF + ((lane & 7) + ((lane >> 3) & 3) * 8) * 144;

            // ---- S = Q K^T (Q split, K single) ----
            float s[8][4];
#pragma unroll
            for (int j = 0; j < 8; j++)
#pragma unroll
                for (int r = 0; r < 4; r++) s[j][r] = 0.f;
#pragma unroll
            for (int kp = 0; kp < 2; kp++) {
#pragma unroll
                for (int jp = 0; jp < 4; jp++) {
                    const int j0 = 2 * jp, j1 = 2 * jp + 1;
                    uint32_t kf0[4], kf1[4];
                    ldmx4(kf0, kaddr0 + j0 * (8 * 144) + kp * 64);
                    ldmx4(kf1, kaddr0 + j1 * (8 * 144) + kp * 64);
                    mma_f16(s[j0], qfh[2 * kp], kf0);       mma_f16(s[j1], qfh[2 * kp], kf1);
                    mma_f16(s[j0], qfl[2 * kp], kf0);       mma_f16(s[j1], qfl[2 * kp], kf1);
                    mma_f16(s[j0], qfh[2 * kp + 1], kf0 + 2); mma_f16(s[j1], qfh[2 * kp + 1], kf1 + 2);
                    mma_f16(s[j0], qfl[2 * kp + 1], kf0 + 2); mma_f16(s[j1], qfl[2 * kp + 1], kf1 + 2);
                }
            }

            // ---- causal mask (diagonal tiles) ----
            if (k0 + 63 > q0w) {
                int gq0 = q0w + (lane >> 2);
                int cb = k0 + 2 * (lane & 3);
#pragma unroll
                for (int j = 0; j < 8; j++) {
                    int c = cb + 8 * j;
                    if (c > gq0)         s[j][0] = -1e30f;
                    if (c + 1 > gq0)     s[j][1] = -1e30f;
                    if (c > gq0 + 8)     s[j][2] = -1e30f;
                    if (c + 1 > gq0 + 8) s[j][3] = -1e30f;
                }
            }

            // ---- online softmax ----
            float mx0 = -1e30f, mx1 = -1e30f;
#pragma unroll
            for (int j = 0; j < 8; j++) {
                mx0 = fmaxf(mx0, fmaxf(s[j][0], s[j][1]));
                mx1 = fmaxf(mx1, fmaxf(s[j][2], s[j][3]));
            }
            mx0 = fmaxf(mx0, __shfl_xor_sync(0xffffffffu, mx0, 1));
            mx0 = fmaxf(mx0, __shfl_xor_sync(0xffffffffu, mx0, 2));
            mx1 = fmaxf(mx1, __shfl_xor_sync(0xffffffffu, mx1, 1));
            mx1 = fmaxf(mx1, __shfl_xor_sync(0xffffffffu, mx1, 2));
            float mn0 = fmaxf(m0v, mx0), mn1 = fmaxf(m1v, mx1);
            float c0 = fast_exp2(m0v - mn0), c1 = fast_exp2(m1v - mn1);
            m0v = mn0; m1v = mn1;

            uint32_t ph[4][4], pl[4][4];
            float rs0 = 0.f, rs1 = 0.f;
#pragma unroll
            for (int j = 0; j < 8; j++) {
                float p0 = fast_exp2(s[j][0] - mn0);
                float p1 = fast_exp2(s[j][1] - mn0);
                float p2 = fast_exp2(s[j][2] - mn1);
                float p3 = fast_exp2(s[j][3] - mn1);
                rs0 += p0 + p1; rs1 += p2 + p3;
                int kc = j >> 1, a0 = (j & 1) * 2;
                uint32_t h01 = packh(p0, p1);
                uint32_t h23 = packh(p2, p3);
                ph[kc][a0] = h01; ph[kc][a0 + 1] = h23;
                pl[kc][a0] = packh_lo(p0, p1, h01);
                pl[kc][a0 + 1] = packh_lo(p2, p3, h23);
            }
            rs0 += __shfl_xor_sync(0xffffffffu, rs0, 1);
            rs0 += __shfl_xor_sync(0xffffffffu, rs0, 2);
            rs1 += __shfl_xor_sync(0xffffffffu, rs1, 1);
            rs1 += __shfl_xor_sync(0xffffffffu, rs1, 2);
            l0v = l0v * c0 + rs0;
            l1v = l1v * c1 + rs1;
#pragma unroll
            for (int j = 0; j < 8; j++) {
                o[j][0] *= c0; o[j][1] *= c0;
                o[j][2] *= c1; o[j][3] *= c1;
            }

            // ---- O += P @ V (P split, V single) ----
#pragma unroll
            for (int kp = 0; kp < 2; kp++) {
#pragma unroll
                for (int jp = 0; jp < 4; jp++) {
                    const int j0 = 2 * jp, j1 = 2 * jp + 1;
                    uint32_t vf0[4], vf1[4];
                    ldmx4t(vf0, vaddr0 + kp * (32 * 144) + j0 * 16);
                    ldmx4t(vf1, vaddr0 + kp * (32 * 144) + j1 * 16);
                    mma_f16(o[j0], ph[2 * kp], vf0);        mma_f16(o[j1], ph[2 * kp], vf1);
                    mma_f16(o[j0], pl[2 * kp], vf0);        mma_f16(o[j1], pl[2 * kp], vf1);
                    mma_f16(o[j0], ph[2 * kp + 1], vf0 + 2); mma_f16(o[j1], ph[2 * kp + 1], vf1 + 2);
                    mma_f16(o[j0], pl[2 * kp + 1], vf0 + 2); mma_f16(o[j1], pl[2 * kp + 1], vf1 + 2);
                }
            }
        }
    }
    cp_wait<0>();

    // ---- epilogue: write y as fp16 hi/lo for the proj GEMM ----
    float inv0 = 1.0f / l0v, inv1 = 1.0f / l1v;
    int gq = q0w + (lane >> 2);
    size_t base0 = ((size_t)((bh >> 4) * T_SEQ + gq)) * C_DIM + (bh & 15) * HD + 2 * (lane & 3);
    size_t base1 = base0 + 8 * C_DIM;
#pragma unroll
    for (int j = 0; j < 8; j++) {
        float f0 = o[j][0] * inv0, f1 = o[j][1] * inv0;
        uint32_t h = packh(f0, f1);
        *(uint32_t*)&yh[base0 + 8 * j] = h;
        *(uint32_t*)&yl[base0 + 8 * j] = packh_lo(f0, f1, h);
        float f2 = o[j][2] * inv1, f3 = o[j][3] * inv1;
        h = packh(f2, f3);
        *(uint32_t*)&yh[base1 + 8 * j] = h;
        *(uint32_t*)&yl[base1 + 8 * j] = packh_lo(f2, f3, h);
    }
}

// ---------------------------------------------------------------------------
extern "C" void kernel_launch(void* const* d_in, const int* in_sizes, int n_in,
                              void* d_out, int out_size) {
    const float* x      = (const float*)d_in[0];
    const float* w_qkv  = (const float*)d_in[1];
    const float* w_proj = (const float*)d_in[2];
    float* out = (float*)d_out;

    float* qkv;
    __nv_bfloat16 *xh, *xl, *wqh, *wql;
    __half *qh, *ql, *k16, *v16, *yh, *yl, *wp16;
    cudaGetSymbolAddress((void**)&qkv, g_qkv);
    cudaGetSymbolAddress((void**)&xh, g_xh);   cudaGetSymbolAddress((void**)&xl, g_xl);
    cudaGetSymbolAddress((void**)&wqh, g_wqh); cudaGetSymbolAddress((void**)&wql, g_wql);
    cudaGetSymbolAddress((void**)&qh, g_qh);   cudaGetSymbolAddress((void**)&ql, g_ql);
    cudaGetSymbolAddress((void**)&k16, g_k16); cudaGetSymbolAddress((void**)&v16, g_v16);
    cudaGetSymbolAddress((void**)&yh, g_yh);   cudaGetSymbolAddress((void**)&yl, g_yl);
    cudaGetSymbolAddress((void**)&wp16, g_wp16);

    cudaFuncSetAttribute(gemm_bf16_v3, cudaFuncAttributeMaxDynamicSharedMemorySize, 3 * GSTG3);
    cudaFuncSetAttribute(gemm_f16_2t, cudaFuncAttributeMaxDynamicSharedMemorySize, 3 * GSTG3);
    cudaFuncSetAttribute(flash_f16, cudaFuncAttributeMaxDynamicSharedMemorySize, 2 * FSTAGE);

    // 0) pre-passes
    split_bf16<<<M_ROWS * C_DIM / 4 / 256, 256>>>(x, xh, xl, M_ROWS * C_DIM / 4);
    split_bf16<<<C3 * C_DIM / 4 / 256, 256>>>(w_qkv, wqh, wql, C3 * C_DIM / 4);
    round_f16<<<C_DIM * C_DIM / 4 / 256, 256>>>(w_proj, wp16, C_DIM * C_DIM / 4);

    // 1) QKV projection (bf16 3-term)
    gemm_bf16_v3<<<dim3(C3 / 128, M_ROWS / 128), 128, 3 * GSTG3>>>(
        xh, xl, wqh, wql, qkv, M_ROWS, C3, C_DIM);

    // 2) RoPE + fp16 split
    rope_split<<<M_ROWS * NH * 16 / 256, 256>>>(qkv, qh, ql, k16, v16);

    // 3) Flash attention (fp16 2-term) -> y fp16 hi/lo
    flash_f16<<<dim3(T_SEQ / 128, 2 * NH), 256, 2 * FSTAGE>>>(
        qh, ql, k16, v16, yh, yl);

    // 4) Output projection (fp16 2-term)
    gemm_f16_2t<<<dim3(C_DIM / 128, M_ROWS / 128), 128, 3 * GSTG3>>>(
        yh, yl, wp16, out, M_ROWS, C_DIM, C_DIM);
}

// round 17
// speedup vs baseline: 1.7751x; 1.1522x over previous
#include <cuda_runtime.h>
#include <cuda_fp16.h>
#include <math.h>
#include <cstdint>

#define T_SEQ 2048
#define C_DIM 1024
#define C3    3072
#define NH    16
#define HD    64
#define M_ROWS 4096   // B*T

// ---------------------------------------------------------------------------
// Scratch (static device arrays — allocation-guard safe)
// ---------------------------------------------------------------------------
__device__ float g_qkv[(size_t)M_ROWS * C3];
__device__ __half g_x16h[(size_t)M_ROWS * C_DIM], g_x16l[(size_t)M_ROWS * C_DIM];
__device__ __half g_wq16[(size_t)C3 * C_DIM];
__device__ __half g_qh[(size_t)2 * NH * T_SEQ * HD], g_ql[(size_t)2 * NH * T_SEQ * HD];
__device__ __half g_k16[(size_t)2 * NH * T_SEQ * HD];
__device__ __half g_v16[(size_t)2 * NH * T_SEQ * HD];
__device__ __half g_yh[(size_t)M_ROWS * C_DIM], g_yl[(size_t)M_ROWS * C_DIM];
__device__ __half g_wp16[(size_t)C_DIM * C_DIM];

// ---------------------------------------------------------------------------
// helpers
// ---------------------------------------------------------------------------
__device__ __forceinline__ uint32_t smem_u32(const void* p) {
    uint32_t a;
    asm("{ .reg .u64 t; cvta.to.shared.u64 t, %1; cvt.u32.u64 %0, t; }"
        : "=r"(a) : "l"(p));
    return a;
}
__device__ __forceinline__ void mma_f16(float* c, const uint32_t* a, const uint32_t* b) {
    asm volatile(
        "mma.sync.aligned.m16n8k16.row.col.f32.f16.f16.f32 "
        "{%0,%1,%2,%3}, {%4,%5,%6,%7}, {%8,%9}, {%0,%1,%2,%3};"
        : "+f"(c[0]), "+f"(c[1]), "+f"(c[2]), "+f"(c[3])
        : "r"(a[0]), "r"(a[1]), "r"(a[2]), "r"(a[3]), "r"(b[0]), "r"(b[1]));
}
__device__ __forceinline__ void mma2_f16(float* c, const uint32_t* a, uint32_t b0, uint32_t b1) {
    asm volatile(
        "mma.sync.aligned.m16n8k16.row.col.f32.f16.f16.f32 "
        "{%0,%1,%2,%3}, {%4,%5,%6,%7}, {%8,%9}, {%0,%1,%2,%3};"
        : "+f"(c[0]), "+f"(c[1]), "+f"(c[2]), "+f"(c[3])
        : "r"(a[0]), "r"(a[1]), "r"(a[2]), "r"(a[3]), "r"(b0), "r"(b1));
}
__device__ __forceinline__ void ldmx4(uint32_t* r, uint32_t addr) {
    asm volatile("ldmatrix.sync.aligned.m8n8.x4.shared.b16 {%0,%1,%2,%3}, [%4];"
        : "=r"(r[0]), "=r"(r[1]), "=r"(r[2]), "=r"(r[3]) : "r"(addr));
}
__device__ __forceinline__ void ldmx4t(uint32_t* r, uint32_t addr) {
    asm volatile("ldmatrix.sync.aligned.m8n8.x4.trans.shared.b16 {%0,%1,%2,%3}, [%4];"
        : "=r"(r[0]), "=r"(r[1]), "=r"(r[2]), "=r"(r[3]) : "r"(addr));
}
__device__ __forceinline__ float fast_exp2(float x) {
    float r;
    asm("ex2.approx.ftz.f32 %0, %1;" : "=f"(r) : "f"(x));
    return r;
}
__device__ __forceinline__ uint32_t packh(float a, float b) {
    __half2 h = __floats2half2_rn(a, b);
    return *(uint32_t*)&h;
}
__device__ __forceinline__ uint32_t packh_lo(float a, float b, uint32_t hi) {
    __half2 h = *(__half2*)&hi;
    float2 f = __half22float2(h);
    __half2 l = __floats2half2_rn(a - f.x, b - f.y);
    return *(uint32_t*)&l;
}
__device__ __forceinline__ void cp16(uint32_t dst, const void* src) {
    asm volatile("cp.async.cg.shared.global [%0], [%1], 16;" :: "r"(dst), "l"(src));
}
__device__ __forceinline__ void cp_commit() {
    asm volatile("cp.async.commit_group;" ::: "memory");
}
template <int N>
__device__ __forceinline__ void cp_wait() {
    asm volatile("cp.async.wait_group %0;" :: "n"(N) : "memory");
}

// ---------------------------------------------------------------------------
// pre-passes
// ---------------------------------------------------------------------------
__global__ __launch_bounds__(256) void split_f16(const float* __restrict__ in,
                                                 __half* __restrict__ hi,
                                                 __half* __restrict__ lo,
                                                 int n4) {
    int i = blockIdx.x * blockDim.x + threadIdx.x;
    if (i >= n4) return;
    float4 v = ((const float4*)in)[i];
    uint32_t h0 = packh(v.x, v.y);
    uint32_t h1 = packh(v.z, v.w);
    ((uint2*)hi)[i] = make_uint2(h0, h1);
    ((uint2*)lo)[i] = make_uint2(packh_lo(v.x, v.y, h0), packh_lo(v.z, v.w, h1));
}

__global__ __launch_bounds__(256) void round_f16(const float* __restrict__ in,
                                                 __half* __restrict__ out, int n4) {
    int i = blockIdx.x * blockDim.x + threadIdx.x;
    if (i >= n4) return;
    float4 v = ((const float4*)in)[i];
    ((uint2*)out)[i] = make_uint2(packh(v.x, v.y), packh(v.z, v.w));
}

// ---------------------------------------------------------------------------
// RoPE + split: qkv fp32 -> per-head fp16 planes.
// q: hi/lo (scaled by 1/8*log2e); k, v: single fp16.
// ---------------------------------------------------------------------------
__global__ __launch_bounds__(256) void rope_split(
    const float* __restrict__ qkv,
    __half* __restrict__ qh, __half* __restrict__ ql,
    __half* __restrict__ k16, __half* __restrict__ v16) {
    int idx = blockIdx.x * 256 + threadIdx.x;
    int g = idx & 15;
    int rowh = idx >> 4;
    int t = rowh & (T_SEQ - 1);
    int bh = rowh >> 11;
    int b = bh >> 4, h = bh & 15;
    const float* base = qkv + ((size_t)(b * T_SEQ + t)) * C3 + h * HD + g * 4;
    float4 q = *(const float4*)base;
    float4 k = *(const float4*)(base + C_DIM);
    float4 v = *(const float4*)(base + 2 * C_DIM);
    int d0 = g * 4;
    float th0 = (float)exp((double)d0 * -0.14391156831212787);
    float th1 = (float)exp((double)(d0 + 2) * -0.14391156831212787);
    float s0, c0, s1, c1;
    sincosf((float)t * th0, &s0, &c0);
    sincosf((float)t * th1, &s1, &c1);
    const float qs = 0.125f * 1.4426950408889634f;
    float qx = (q.x * c0 - q.y * s0) * qs, qy = (q.y * c0 + q.x * s0) * qs;
    float qz = (q.z * c1 - q.w * s1) * qs, qw = (q.w * c1 + q.z * s1) * qs;
    float kx = k.x * c0 - k.y * s0, ky = k.y * c0 + k.x * s0;
    float kz = k.z * c1 - k.w * s1, kw = k.w * c1 + k.z * s1;
    size_t oi = (size_t)rowh * 16 + g;
    uint32_t h0 = packh(qx, qy), h1 = packh(qz, qw);
    ((uint2*)qh)[oi] = make_uint2(h0, h1);
    ((uint2*)ql)[oi] = make_uint2(packh_lo(qx, qy, h0), packh_lo(qz, qw, h1));
    ((uint2*)k16)[oi] = make_uint2(packh(kx, ky), packh(kz, kw));
    ((uint2*)v16)[oi] = make_uint2(packh(v.x, v.y), packh(v.z, v.w));
}

// ---------------------------------------------------------------------------
// GEMM (NT): fp16 2-term asymmetric. A = hi+lo fp16 planes, B = single fp16.
// CTA 128x128, 4 warps (2x2 of 64x64), K-tile 32, 3-stage cp.async ring with
// uniform group accounting. Row: [A: hi 64B | lo 64B | pad] / [B: 64B data].
// ---------------------------------------------------------------------------
#define GSTG3 36864   // 256 rows * 144B per stage

__global__ __launch_bounds__(128, 2) void gemm_f16_2t(
    const __half* __restrict__ Ah, const __half* __restrict__ Al,
    const __half* __restrict__ Bh,
    float* __restrict__ C, int M, int N, int K) {
    extern __shared__ char smem[];
    const uint32_t sb = smem_u32(smem);
    const int tid = threadIdx.x;
    const int wid = tid >> 5, lane = tid & 31;
    const int wm = wid >> 1, wn = wid & 1;
    const int m0 = blockIdx.y * 128, n0 = blockIdx.x * 128;

    float acc[4][8][4];
#pragma unroll
    for (int i = 0; i < 4; i++)
#pragma unroll
        for (int j = 0; j < 8; j++)
#pragma unroll
            for (int r = 0; r < 4; r++) acc[i][j][r] = 0.f;

    auto issue_tile = [&](int kt, int stg) {
        uint32_t base = sb + stg * GSTG3;
#pragma unroll
        for (int i = 0; i < 12; i++) {   // 1024 A-chunks + 512 B-chunks
            int c = i * 128 + tid;
            const __half* src;
            uint32_t dst;
            if (c < 1024) {
                int row = c >> 3, ch = c & 7;
                dst = base + row * 144 + ch * 16;
                src = (ch < 4 ? Ah : Al) + (size_t)(m0 + row) * K + kt + (ch & 3) * 8;
            } else {
                int cc = c - 1024;
                int row = 128 + (cc >> 2), ch = cc & 3;
                dst = base + row * 144 + ch * 16;
                src = Bh + (size_t)(n0 + row - 128) * K + kt + ch * 8;
            }
            cp16(dst, src);
        }
        cp_commit();
    };

    const int nk = K >> 5;
    issue_tile(0, 0);
    issue_tile(32, 1);

    const uint32_t a_off = (uint32_t)((wm * 64 + (lane & 15)) * 144 + (lane >> 4) * 16);
    const uint32_t b_off = (uint32_t)((128 + wn * 64 + (lane & 15)) * 144 + (lane >> 4) * 16);

    int stg = 0;
    for (int kt = 0; kt < nk; kt++) {
        cp_wait<1>();
        __syncthreads();
        if (kt + 2 < nk) {
            int ns = stg + 2; if (ns >= 3) ns -= 3;
            issue_tile((kt + 2) << 5, ns);
        } else {
            cp_commit();
        }

        const uint32_t tb = sb + stg * GSTG3;
#pragma unroll
        for (int ks = 0; ks < 2; ks++) {
            uint32_t bh4[4][4];
#pragma unroll
            for (int np = 0; np < 4; np++)
                ldmx4(bh4[np], tb + b_off + np * (16 * 144) + ks * 32);
#pragma unroll
            for (int mt = 0; mt < 4; mt++) {
                uint32_t ahi[4], alo[4];
                uint32_t aa = tb + a_off + mt * (16 * 144) + ks * 32;
                ldmx4(ahi, aa);
                ldmx4(alo, aa + 64);
#pragma unroll
                for (int nt = 0; nt < 8; nt++)
                    mma2_f16(acc[mt][nt], ahi, bh4[nt >> 1][nt & 1], bh4[nt >> 1][(nt & 1) + 2]);
#pragma unroll
                for (int nt = 0; nt < 8; nt++)
                    mma2_f16(acc[mt][nt], alo, bh4[nt >> 1][nt & 1], bh4[nt >> 1][(nt & 1) + 2]);
            }
        }
        if (++stg == 3) stg = 0;
    }
    cp_wait<0>();

#pragma unroll
    for (int mt = 0; mt < 4; mt++) {
#pragma unroll
        for (int nt = 0; nt < 8; nt++) {
            int gm = m0 + wm * 64 + mt * 16 + (lane >> 2);
            int gn = n0 + wn * 64 + nt * 8 + (lane & 3) * 2;
            *(float2*)&C[(size_t)gm * N + gn] = make_float2(acc[mt][nt][0], acc[mt][nt][1]);
            *(float2*)&C[(size_t)(gm + 8) * N + gn] = make_float2(acc[mt][nt][2], acc[mt][nt][3]);
        }
    }
}

// ---------------------------------------------------------------------------
// Flash attention, fp16 2-term. Q 128x64/CTA (8 warps x 16 rows), K/V 64x64.
// Q split hi/lo; K, V single fp16. K rows 0-63, V rows 64-127, 144B rows.
// 2-stage cp.async, single sync/tile. NO register cap (spills are deadly).
// ---------------------------------------------------------------------------
#define FSTAGE 18432   // 128 rows * 144B
#define VOFF   (64 * 144)

__global__ __launch_bounds__(256) void flash_f16(
    const __half* __restrict__ qh, const __half* __restrict__ ql,
    const __half* __restrict__ k16, const __half* __restrict__ v16,
    __half* __restrict__ yh, __half* __restrict__ yl) {
    extern __shared__ char smem[];
    const uint32_t sb = smem_u32(smem);
    const int tid = threadIdx.x;
    const int wid = tid >> 5, lane = tid & 31;
    const int qi = gridDim.x - 1 - blockIdx.x;
    const int q0 = qi * 128;
    const int bh = blockIdx.y;
    const size_t hT = (size_t)bh << 11;

    // ---- stage Q into stage area (rows 272B: hi 128B | lo 128B | pad) ----
#pragma unroll
    for (int i = 0; i < 8; i++) {
        int c = i * 256 + tid;
        int row = c >> 4, ch = c & 15;
        uint32_t dst = sb + row * 272 + ch * 16;
        const __half* src = (ch < 8 ? qh : ql) + (hT + q0 + row) * HD + (ch & 7) * 8;
        cp16(dst, src);
    }
    cp_commit();
    cp_wait<0>();
    __syncthreads();

    uint32_t qfh[4][4], qfl[4][4];
    {
        uint32_t qaddr = sb + (wid * 16 + (lane & 15)) * 272 + (lane >> 4) * 16;
#pragma unroll
        for (int kc = 0; kc < 4; kc++) {
            ldmx4(qfh[kc], qaddr + kc * 32);
            ldmx4(qfl[kc], qaddr + kc * 32 + 128);
        }
    }
    __syncthreads();   // Q stage area now reusable as K/V buffers

    auto issue_kv = [&](int k0, int stg) {
        uint32_t base = sb + stg * FSTAGE;
#pragma unroll
        for (int i = 0; i < 4; i++) {
            int c = i * 256 + tid;          // 0..1023
            int row = c >> 3, ch = c & 7;
            uint32_t dst = base + row * 144 + ch * 16;
            const __half* p;
            if (row < 64) p = k16 + (hT + k0 + row) * HD + ch * 8;
            else          p = v16 + (hT + k0 + row - 64) * HD + ch * 8;
            cp16(dst, p);
        }
        cp_commit();
    };
    issue_kv(0, 0);

    float o[8][4];
#pragma unroll
    for (int j = 0; j < 8; j++)
#pragma unroll
        for (int r = 0; r < 4; r++) o[j][r] = 0.f;
    float m0v = -1e30f, m1v = -1e30f, l0v = 0.f, l1v = 0.f;

    const int q0w = q0 + wid * 16;
    const int nkt = 2 * qi + 2;

    for (int kt = 0; kt < nkt; kt++) {
        cp_wait<0>();
        __syncthreads();
        if (kt + 1 < nkt) issue_kv((kt + 1) * 64, (kt + 1) & 1);
        const int k0 = kt * 64;

        if (k0 <= q0w + 15) {
            const uint32_t bb = sb + (kt & 1) * FSTAGE;
            const uint32_t kaddr0 = bb + (lane & 7) * 144 + ((lane >> 3) & 1) * 16 + (lane >> 4) * 32;
            const uint32_t vaddr0 = bb + VOFF + ((lane & 7) + ((lane >> 3) & 3) * 8) * 144;

            // ---- S = Q K^T (Q split, K single) ----
            float s[8][4];
#pragma unroll
            for (int j = 0; j < 8; j++)
#pragma unroll
                for (int r = 0; r < 4; r++) s[j][r] = 0.f;
#pragma unroll
            for (int kp = 0; kp < 2; kp++) {
#pragma unroll
                for (int jp = 0; jp < 4; jp++) {
                    const int j0 = 2 * jp, j1 = 2 * jp + 1;
                    uint32_t kf0[4], kf1[4];
                    ldmx4(kf0, kaddr0 + j0 * (8 * 144) + kp * 64);
                    ldmx4(kf1, kaddr0 + j1 * (8 * 144) + kp * 64);
                    mma_f16(s[j0], qfh[2 * kp], kf0);       mma_f16(s[j1], qfh[2 * kp], kf1);
                    mma_f16(s[j0], qfl[2 * kp], kf0);       mma_f16(s[j1], qfl[2 * kp], kf1);
                    mma_f16(s[j0], qfh[2 * kp + 1], kf0 + 2); mma_f16(s[j1], qfh[2 * kp + 1], kf1 + 2);
                    mma_f16(s[j0], qfl[2 * kp + 1], kf0 + 2); mma_f16(s[j1], qfl[2 * kp + 1], kf1 + 2);
                }
            }

            // ---- causal mask (diagonal tiles) ----
            if (k0 + 63 > q0w) {
                int gq0 = q0w + (lane >> 2);
                int cb = k0 + 2 * (lane & 3);
#pragma unroll
                for (int j = 0; j < 8; j++) {
                    int c = cb + 8 * j;
                    if (c > gq0)         s[j][0] = -1e30f;
                    if (c + 1 > gq0)     s[j][1] = -1e30f;
                    if (c > gq0 + 8)     s[j][2] = -1e30f;
                    if (c + 1 > gq0 + 8) s[j][3] = -1e30f;
                }
            }

            // ---- online softmax ----
            float mx0 = -1e30f, mx1 = -1e30f;
#pragma unroll
            for (int j = 0; j < 8; j++) {
                mx0 = fmaxf(mx0, fmaxf(s[j][0], s[j][1]));
                mx1 = fmaxf(mx1, fmaxf(s[j][2], s[j][3]));
            }
            mx0 = fmaxf(mx0, __shfl_xor_sync(0xffffffffu, mx0, 1));
            mx0 = fmaxf(mx0, __shfl_xor_sync(0xffffffffu, mx0, 2));
            mx1 = fmaxf(mx1, __shfl_xor_sync(0xffffffffu, mx1, 1));
            mx1 = fmaxf(mx1, __shfl_xor_sync(0xffffffffu, mx1, 2));
            float mn0 = fmaxf(m0v, mx0), mn1 = fmaxf(m1v, mx1);
            float c0 = fast_exp2(m0v - mn0), c1 = fast_exp2(m1v - mn1);
            m0v = mn0; m1v = mn1;

            uint32_t ph[4][4], pl[4][4];
            float rs0 = 0.f, rs1 = 0.f;
#pragma unroll
            for (int j = 0; j < 8; j++) {
                float p0 = fast_exp2(s[j][0] - mn0);
                float p1 = fast_exp2(s[j][1] - mn0);
                float p2 = fast_exp2(s[j][2] - mn1);
                float p3 = fast_exp2(s[j][3] - mn1);
                rs0 += p0 + p1; rs1 += p2 + p3;
                int kc = j >> 1, a0 = (j & 1) * 2;
                uint32_t h01 = packh(p0, p1);
                uint32_t h23 = packh(p2, p3);
                ph[kc][a0] = h01; ph[kc][a0 + 1] = h23;
                pl[kc][a0] = packh_lo(p0, p1, h01);
                pl[kc][a0 + 1] = packh_lo(p2, p3, h23);
            }
            rs0 += __shfl_xor_sync(0xffffffffu, rs0, 1);
            rs0 += __shfl_xor_sync(0xffffffffu, rs0, 2);
            rs1 += __shfl_xor_sync(0xffffffffu, rs1, 1);
            rs1 += __shfl_xor_sync(0xffffffffu, rs1, 2);
            l0v = l0v * c0 + rs0;
            l1v = l1v * c1 + rs1;
#pragma unroll
            for (int j = 0; j < 8; j++) {
                o[j][0] *= c0; o[j][1] *= c0;
                o[j][2] *= c1; o[j][3] *= c1;
            }

            // ---- O += P @ V (P split, V single) ----
#pragma unroll
            for (int kp = 0; kp < 2; kp++) {
#pragma unroll
                for (int jp = 0; jp < 4; jp++) {
                    const int j0 = 2 * jp, j1 = 2 * jp + 1;
                    uint32_t vf0[4], vf1[4];
                    ldmx4t(vf0, vaddr0 + kp * (32 * 144) + j0 * 16);
                    ldmx4t(vf1, vaddr0 + kp * (32 * 144) + j1 * 16);
                    mma_f16(o[j0], ph[2 * kp], vf0);        mma_f16(o[j1], ph[2 * kp], vf1);
                    mma_f16(o[j0], pl[2 * kp], vf0);        mma_f16(o[j1], pl[2 * kp], vf1);
                    mma_f16(o[j0], ph[2 * kp + 1], vf0 + 2); mma_f16(o[j1], ph[2 * kp + 1], vf1 + 2);
                    mma_f16(o[j0], pl[2 * kp + 1], vf0 + 2); mma_f16(o[j1], pl[2 * kp + 1], vf1 + 2);
                }
            }
        }
    }
    cp_wait<0>();

    // ---- epilogue: write y as fp16 hi/lo for the proj GEMM ----
    float inv0 = 1.0f / l0v, inv1 = 1.0f / l1v;
    int gq = q0w + (lane >> 2);
    size_t base0 = ((size_t)((bh >> 4) * T_SEQ + gq)) * C_DIM + (bh & 15) * HD + 2 * (lane & 3);
    size_t base1 = base0 + 8 * C_DIM;
#pragma unroll
    for (int j = 0; j < 8; j++) {
        float f0 = o[j][0] * inv0, f1 = o[j][1] * inv0;
        uint32_t h = packh(f0, f1);
        *(uint32_t*)&yh[base0 + 8 * j] = h;
        *(uint32_t*)&yl[base0 + 8 * j] = packh_lo(f0, f1, h);
        float f2 = o[j][2] * inv1, f3 = o[j][3] * inv1;
        h = packh(f2, f3);
        *(uint32_t*)&yh[base1 + 8 * j] = h;
        *(uint32_t*)&yl[base1 + 8 * j] = packh_lo(f2, f3, h);
    }
}

// ---------------------------------------------------------------------------
extern "C" void kernel_launch(void* const* d_in, const int* in_sizes, int n_in,
                              void* d_out, int out_size) {
    const float* x      = (const float*)d_in[0];
    const float* w_qkv  = (const float*)d_in[1];
    const float* w_proj = (const float*)d_in[2];
    float* out = (float*)d_out;

    float* qkv;
    __half *x16h, *x16l, *wq16, *qh, *ql, *k16, *v16, *yh, *yl, *wp16;
    cudaGetSymbolAddress((void**)&qkv, g_qkv);
    cudaGetSymbolAddress((void**)&x16h, g_x16h); cudaGetSymbolAddress((void**)&x16l, g_x16l);
    cudaGetSymbolAddress((void**)&wq16, g_wq16);
    cudaGetSymbolAddress((void**)&qh, g_qh);   cudaGetSymbolAddress((void**)&ql, g_ql);
    cudaGetSymbolAddress((void**)&k16, g_k16); cudaGetSymbolAddress((void**)&v16, g_v16);
    cudaGetSymbolAddress((void**)&yh, g_yh);   cudaGetSymbolAddress((void**)&yl, g_yl);
    cudaGetSymbolAddress((void**)&wp16, g_wp16);

    cudaFuncSetAttribute(gemm_f16_2t, cudaFuncAttributeMaxDynamicSharedMemorySize, 3 * GSTG3);
    cudaFuncSetAttribute(flash_f16, cudaFuncAttributeMaxDynamicSharedMemorySize, 2 * FSTAGE);

    // 0) pre-passes
    split_f16<<<M_ROWS * C_DIM / 4 / 256, 256>>>(x, x16h, x16l, M_ROWS * C_DIM / 4);
    round_f16<<<C3 * C_DIM / 4 / 256, 256>>>(w_qkv, wq16, C3 * C_DIM / 4);
    round_f16<<<C_DIM * C_DIM / 4 / 256, 256>>>(w_proj, wp16, C_DIM * C_DIM / 4);

    // 1) QKV projection (fp16 2-term)
    gemm_f16_2t<<<dim3(C3 / 128, M_ROWS / 128), 128, 3 * GSTG3>>>(
        x16h, x16l, wq16, qkv, M_ROWS, C3, C_DIM);

    // 2) RoPE + fp16 split
    rope_split<<<M_ROWS * NH * 16 / 256, 256>>>(qkv, qh, ql, k16, v16);

    // 3) Flash attention (fp16 2-term) -> y fp16 hi/lo
    flash_f16<<<dim3(T_SEQ / 128, 2 * NH), 256, 2 * FSTAGE>>>(
        qh, ql, k16, v16, yh, yl);

    // 4) Output projection (fp16 2-term)
    gemm_f16_2t<<<dim3(C_DIM / 128, M_ROWS / 128), 128, 3 * GSTG3>>>(
        yh, yl, wp16, out, M_ROWS, C_DIM, C_DIM);
}